// round 7
// baseline (speedup 1.0000x reference)
#include <cuda_runtime.h>
#include <cuda_fp16.h>

#define DIM   128
#define NC    4
#define N_RNA_MAX  20000
#define N_PROT_MAX 5000

// Folded weights: M[j][d] = sum_c Wc[c][j] * w_rel[c][d]
__device__ float g_M[NC * DIM];
// fp16 copies of the gather tables (halves L2 gather traffic; 500K edges
// x 1KB fp32 = 512MB of L2 flow is exactly the LTS chip cap at ~40us).
__device__ __half g_rna [N_RNA_MAX  * DIM];
__device__ __half g_prot[N_PROT_MAX * DIM];

__global__ void fold_weights_kernel(const float* __restrict__ w_rel,
                                    const float* __restrict__ w_cls) {
    int t = threadIdx.x;
    if (t < NC * DIM) {
        int j = t / DIM, d = t % DIM;
        float s = 0.f;
#pragma unroll
        for (int c = 0; c < NC; ++c)
            s += w_cls[c * NC + j] * w_rel[c * DIM + d];
        g_M[j * DIM + d] = s;
    }
}

// Convert both fp32 tables to fp16. Each thread handles 8 elements.
__global__ __launch_bounds__(256) void cvt_kernel(
    const float* __restrict__ rna, const float* __restrict__ prot,
    long long nRelem, long long nPelem)
{
    long long i = (long long)blockIdx.x * blockDim.x + threadIdx.x;
    long long base = i * 8;
    if (base >= nRelem + nPelem) return;
    const float* src;  __half* dst;  long long off;
    if (base < nRelem) { src = rna;  dst = g_rna;  off = base; }
    else               { src = prot; dst = g_prot; off = base - nRelem; }

    float4 f0 = *reinterpret_cast<const float4*>(src + off);
    float4 f1 = *reinterpret_cast<const float4*>(src + off + 4);
    __half2 h0 = __floats2half2_rn(f0.x, f0.y);
    __half2 h1 = __floats2half2_rn(f0.z, f0.w);
    __half2 h2 = __floats2half2_rn(f1.x, f1.y);
    __half2 h3 = __floats2half2_rn(f1.z, f1.w);
    uint4 o;
    o.x = *reinterpret_cast<unsigned*>(&h0);
    o.y = *reinterpret_cast<unsigned*>(&h1);
    o.z = *reinterpret_cast<unsigned*>(&h2);
    o.w = *reinterpret_cast<unsigned*>(&h3);
    *reinterpret_cast<uint4*>(dst + off) = o;
}

// Streaming 16B load (guaranteed-miss gathers: skip L1 allocate).
__device__ __forceinline__ uint4 ldg_na(const uint4* p) {
    uint4 v;
    asm("ld.global.L1::no_allocate.v4.u32 {%0,%1,%2,%3}, [%4];"
        : "=r"(v.x), "=r"(v.y), "=r"(v.z), "=r"(v.w) : "l"(p));
    return v;
}

// Class-split butterfly over lane bits 0-1 (3 shfl). Afterwards lane l holds
// class c = ((l&1)<<1)|((l>>1)&1) summed over its 4-lane group.
__device__ __forceinline__ float reduce_stage1(const float a[4], int lane) {
    float x = (lane & 1) ? a[0] : a[2];
    float y = (lane & 1) ? a[1] : a[3];
    float rx = __shfl_xor_sync(0xffffffffu, x, 1);
    float ry = __shfl_xor_sync(0xffffffffu, y, 1);
    float A = ((lane & 1) ? a[2] : a[0]) + rx;
    float B = ((lane & 1) ? a[3] : a[1]) + ry;
    float z = (lane & 2) ? A : B;
    float rz = __shfl_xor_sync(0xffffffffu, z, 2);
    return ((lane & 2) ? B : A) + rz;
}

// Multiply 8 fp16 pairs (fp32 math) and accumulate 4 class dots.
__device__ __forceinline__ void accum_edge(uint4 R, uint4 P,
                                           const float4 Ma[NC], const float4 Mb[NC],
                                           float a[NC]) {
    float2 r0 = __half22float2(*reinterpret_cast<__half2*>(&R.x));
    float2 r1 = __half22float2(*reinterpret_cast<__half2*>(&R.y));
    float2 r2 = __half22float2(*reinterpret_cast<__half2*>(&R.z));
    float2 r3 = __half22float2(*reinterpret_cast<__half2*>(&R.w));
    float2 p0 = __half22float2(*reinterpret_cast<__half2*>(&P.x));
    float2 p1 = __half22float2(*reinterpret_cast<__half2*>(&P.y));
    float2 p2 = __half22float2(*reinterpret_cast<__half2*>(&P.z));
    float2 p3 = __half22float2(*reinterpret_cast<__half2*>(&P.w));
    float q0 = r0.x * p0.x, q1 = r0.y * p0.y;
    float q2 = r1.x * p1.x, q3 = r1.y * p1.y;
    float q4 = r2.x * p2.x, q5 = r2.y * p2.y;
    float q6 = r3.x * p3.x, q7 = r3.y * p3.y;
#pragma unroll
    for (int j = 0; j < NC; ++j) {
        a[j] += q0 * Ma[j].x + q1 * Ma[j].y + q2 * Ma[j].z + q3 * Ma[j].w
              + q4 * Mb[j].x + q5 * Mb[j].y + q6 * Mb[j].z + q7 * Mb[j].w;
    }
}

// 16 lanes per edge (lane h owns halves 8h..8h+7 = one 16B load per table);
// each warp handles 4 edges: halfwarp `sub` owns edges 4w+sub and 4w+2+sub.
__global__ __launch_bounds__(256) void edge_kernel(
    const int* __restrict__ ridx,
    const int* __restrict__ pidx,
    float* __restrict__ out,
    int E)
{
    const int lane = threadIdx.x & 31;
    const int h    = lane & 15;
    const int sub  = lane >> 4;
    const int w    = (blockIdx.x * blockDim.x + threadIdx.x) >> 5;

    // Folded-weight slice for this lane: M[j][8h..8h+7] = 2 float4 per class.
    const float4* Mv = reinterpret_cast<const float4*>(g_M);
    float4 Ma[NC], Mb[NC];
#pragma unroll
    for (int j = 0; j < NC; ++j) {
        Ma[j] = Mv[j * (DIM / 4) + 2 * h];
        Mb[j] = Mv[j * (DIM / 4) + 2 * h + 1];
    }

    const int e0 = 4 * w + sub;
    const int e1 = e0 + 2;
    const int ee0 = (e0 < E) ? e0 : 0;
    const int ee1 = (e1 < E) ? e1 : 0;

    const int ri0 = ridx[ee0], pi0 = pidx[ee0];
    const int ri1 = ridx[ee1], pi1 = pidx[ee1];

    const uint4* rv = reinterpret_cast<const uint4*>(g_rna);
    const uint4* pv = reinterpret_cast<const uint4*>(g_prot);

    // 4 gathers in flight per lane; each warp load = 256B contiguous per
    // halfwarp (full fp16 row) -> perfectly coalesced.
    uint4 R0 = ldg_na(rv + (long long)ri0 * 16 + h);
    uint4 P0 = ldg_na(pv + (long long)pi0 * 16 + h);
    uint4 R1 = ldg_na(rv + (long long)ri1 * 16 + h);
    uint4 P1 = ldg_na(pv + (long long)pi1 * 16 + h);

    float a0[NC] = {0.f, 0.f, 0.f, 0.f};
    float a1[NC] = {0.f, 0.f, 0.f, 0.f};
    accum_edge(R0, P0, Ma, Mb, a0);
    accum_edge(R1, P1, Ma, Mb, a1);

    // Per-edge reduction within the halfwarp: 3 + 2 shfl each.
    float S0 = reduce_stage1(a0, lane);
    S0 += __shfl_xor_sync(0xffffffffu, S0, 4);
    S0 += __shfl_xor_sync(0xffffffffu, S0, 8);
    float S1 = reduce_stage1(a1, lane);
    S1 += __shfl_xor_sync(0xffffffffu, S1, 4);
    S1 += __shfl_xor_sync(0xffffffffu, S1, 8);

    if (h < 4) {
        const int c = ((h & 1) << 1) | ((h >> 1) & 1);
        if (e0 < E) out[4 * e0 + c] = fmaxf(S0, 0.f);
        if (e1 < E) out[4 * e1 + c] = fmaxf(S1, 0.f);
    }
}

extern "C" void kernel_launch(void* const* d_in, const int* in_sizes, int n_in,
                              void* d_out, int out_size) {
    const float* rna  = (const float*)d_in[0];   // [20000,128] f32
    const float* prot = (const float*)d_in[1];   // [5000,128]  f32
    const int*   ridx = (const int*)d_in[2];     // [E] int32
    const int*   pidx = (const int*)d_in[3];     // [E] int32
    const float* wrel = (const float*)d_in[4];   // [4,128] f32
    const float* wcls = (const float*)d_in[5];   // [4,4]   f32
    float*       out  = (float*)d_out;           // [E,4]   f32

    const int E = in_sizes[2];
    const long long nRelem = in_sizes[0];
    const long long nPelem = in_sizes[1];

    fold_weights_kernel<<<1, NC * DIM>>>(wrel, wcls);

    const long long groups = (nRelem + nPelem) / 8;
    const int cvt_blocks = (int)((groups + 255) / 256);
    cvt_kernel<<<cvt_blocks, 256>>>(rna, prot, nRelem, nPelem);

    const long long warps  = ((long long)E + 3) / 4;
    const long long blocks = (warps + 7) / 8;
    edge_kernel<<<(int)blocks, 256>>>(ridx, pidx, out, E);
}

// round 8
// speedup vs baseline: 2.2055x; 2.2055x over previous
#include <cuda_runtime.h>
#include <cuda_fp16.h>

#define DIM   128
#define NC    4
#define N_RNA_MAX  20000
#define N_PROT_MAX 5000

// Folded weights: M[j][d] = sum_c Wc[c][j] * w_rel[c][d]
__device__ float g_M[NC * DIM];
// fp16 copies of the gather tables: halves the ~512MB L2 gather flow that
// capped the fp32 kernels at ~40us (LTS ~6300 B/cyc chip-wide).
__device__ __half g_rna [N_RNA_MAX  * DIM];
__device__ __half g_prot[N_PROT_MAX * DIM];

// One prologue kernel: folds weights (first 512 threads) and converts both
// tables to fp16 (grid covers (nR+nP)/8 threads, 8 elems each).
__global__ __launch_bounds__(256) void prep_kernel(
    const float* __restrict__ rna, const float* __restrict__ prot,
    const float* __restrict__ w_rel, const float* __restrict__ w_cls,
    long long nRelem, long long nPelem)
{
    const long long i = (long long)blockIdx.x * blockDim.x + threadIdx.x;

    if (i < NC * DIM) {
        int j = (int)i / DIM, d = (int)i % DIM;
        float s = 0.f;
#pragma unroll
        for (int c = 0; c < NC; ++c)
            s += w_cls[c * NC + j] * w_rel[c * DIM + d];
        g_M[j * DIM + d] = s;
    }

    const long long base = i * 8;
    if (base >= nRelem + nPelem) return;
    const float* src;  __half* dst;  long long off;
    if (base < nRelem) { src = rna;  dst = g_rna;  off = base; }
    else               { src = prot; dst = g_prot; off = base - nRelem; }

    float4 f0 = *reinterpret_cast<const float4*>(src + off);
    float4 f1 = *reinterpret_cast<const float4*>(src + off + 4);
    __half2 h0 = __floats2half2_rn(f0.x, f0.y);
    __half2 h1 = __floats2half2_rn(f0.z, f0.w);
    __half2 h2 = __floats2half2_rn(f1.x, f1.y);
    __half2 h3 = __floats2half2_rn(f1.z, f1.w);
    uint4 o;
    o.x = *reinterpret_cast<unsigned*>(&h0);
    o.y = *reinterpret_cast<unsigned*>(&h1);
    o.z = *reinterpret_cast<unsigned*>(&h2);
    o.w = *reinterpret_cast<unsigned*>(&h3);
    *reinterpret_cast<uint4*>(dst + off) = o;
}

// Streaming 16B load (guaranteed-miss gathers: skip L1 allocate).
__device__ __forceinline__ uint4 ldg_na(const uint4* p) {
    uint4 v;
    asm("ld.global.L1::no_allocate.v4.u32 {%0,%1,%2,%3}, [%4];"
        : "=r"(v.x), "=r"(v.y), "=r"(v.z), "=r"(v.w) : "l"(p));
    return v;
}

// Class-split butterfly over lane bits 0-1 (3 shfl). Afterwards lane l holds
// class c = ((l&1)<<1)|((l>>1)&1) summed over its 4-lane group.
__device__ __forceinline__ float reduce_stage1(const float a[4], int lane) {
    float x = (lane & 1) ? a[0] : a[2];
    float y = (lane & 1) ? a[1] : a[3];
    float rx = __shfl_xor_sync(0xffffffffu, x, 1);
    float ry = __shfl_xor_sync(0xffffffffu, y, 1);
    float A = ((lane & 1) ? a[2] : a[0]) + rx;
    float B = ((lane & 1) ? a[3] : a[1]) + ry;
    float z = (lane & 2) ? A : B;
    float rz = __shfl_xor_sync(0xffffffffu, z, 2);
    return ((lane & 2) ? B : A) + rz;
}

// fp16 product, fp32 accumulate: 4 hmul2 + 4 cvt per edge per lane (half the
// conversions of converting r and p separately).
__device__ __forceinline__ void accum_edge(uint4 R, uint4 P,
                                           const float4 Ma[NC], const float4 Mb[NC],
                                           float a[NC]) {
    __half2 q0 = __hmul2(*reinterpret_cast<__half2*>(&R.x),
                         *reinterpret_cast<__half2*>(&P.x));
    __half2 q1 = __hmul2(*reinterpret_cast<__half2*>(&R.y),
                         *reinterpret_cast<__half2*>(&P.y));
    __half2 q2 = __hmul2(*reinterpret_cast<__half2*>(&R.z),
                         *reinterpret_cast<__half2*>(&P.z));
    __half2 q3 = __hmul2(*reinterpret_cast<__half2*>(&R.w),
                         *reinterpret_cast<__half2*>(&P.w));
    float2 f0 = __half22float2(q0);
    float2 f1 = __half22float2(q1);
    float2 f2 = __half22float2(q2);
    float2 f3 = __half22float2(q3);
#pragma unroll
    for (int j = 0; j < NC; ++j) {
        a[j] += f0.x * Ma[j].x + f0.y * Ma[j].y + f1.x * Ma[j].z + f1.y * Ma[j].w
              + f2.x * Mb[j].x + f2.y * Mb[j].y + f3.x * Mb[j].z + f3.y * Mb[j].w;
    }
}

// 16 lanes per edge (lane h owns halves 8h..8h+7 = one 16B load per table);
// each halfwarp handles 4 edges -> 8 gathers (128B) in flight per lane.
__global__ __launch_bounds__(256) void edge_kernel(
    const int* __restrict__ ridx,
    const int* __restrict__ pidx,
    float* __restrict__ out,
    int E)
{
    const int lane = threadIdx.x & 31;
    const int h    = lane & 15;
    const int sub  = lane >> 4;
    const int w    = (blockIdx.x * blockDim.x + threadIdx.x) >> 5;

    // Folded-weight slice for this lane: M[j][8h..8h+7] = 2 float4 per class.
    const float4* Mv = reinterpret_cast<const float4*>(g_M);
    float4 Ma[NC], Mb[NC];
#pragma unroll
    for (int j = 0; j < NC; ++j) {
        Ma[j] = Mv[j * (DIM / 4) + 2 * h];
        Mb[j] = Mv[j * (DIM / 4) + 2 * h + 1];
    }

    const uint4* rv = reinterpret_cast<const uint4*>(g_rna);
    const uint4* pv = reinterpret_cast<const uint4*>(g_prot);

    // 4 edges per halfwarp: e_i = 8w + 4*sub + i
    int e[4];
    uint4 R[4], P[4];
#pragma unroll
    for (int i = 0; i < 4; ++i) {
        e[i] = 8 * w + 4 * sub + i;
        const int ec = (e[i] < E) ? e[i] : 0;
        const int ri = ridx[ec];
        const int pi = pidx[ec];
        R[i] = ldg_na(rv + (long long)ri * 16 + h);
        P[i] = ldg_na(pv + (long long)pi * 16 + h);
    }

    float a[4][NC];
#pragma unroll
    for (int i = 0; i < 4; ++i) {
#pragma unroll
        for (int j = 0; j < NC; ++j) a[i][j] = 0.f;
        accum_edge(R[i], P[i], Ma, Mb, a[i]);
    }

#pragma unroll
    for (int i = 0; i < 4; ++i) {
        // 3-shfl class split + fold the 16-lane halfwarp (masks <16 stay
        // within the halfwarp).
        float S = reduce_stage1(a[i], lane);
        S += __shfl_xor_sync(0xffffffffu, S, 4);
        S += __shfl_xor_sync(0xffffffffu, S, 8);
        if (h < 4 && e[i] < E) {
            const int c = ((h & 1) << 1) | ((h >> 1) & 1);
            out[4 * e[i] + c] = fmaxf(S, 0.f);
        }
    }
}

extern "C" void kernel_launch(void* const* d_in, const int* in_sizes, int n_in,
                              void* d_out, int out_size) {
    const float* rna  = (const float*)d_in[0];   // [20000,128] f32
    const float* prot = (const float*)d_in[1];   // [5000,128]  f32
    const int*   ridx = (const int*)d_in[2];     // [E] int32
    const int*   pidx = (const int*)d_in[3];     // [E] int32
    const float* wrel = (const float*)d_in[4];   // [4,128] f32
    const float* wcls = (const float*)d_in[5];   // [4,4]   f32
    float*       out  = (float*)d_out;           // [E,4]   f32

    const int E = in_sizes[2];
    const long long nRelem = in_sizes[0];
    const long long nPelem = in_sizes[1];

    const long long cvt_threads = (nRelem + nPelem + 7) / 8;
    const int prep_blocks = (int)((cvt_threads + 255) / 256);
    prep_kernel<<<prep_blocks, 256>>>(rna, prot, wrel, wcls, nRelem, nPelem);

    // 8 edges per warp, 8 warps per block.
    const long long warps  = ((long long)E + 7) / 8;
    const long long blocks = (warps + 7) / 8;
    edge_kernel<<<(int)blocks, 256>>>(ridx, pidx, out, E);
}

// round 9
// speedup vs baseline: 2.3354x; 1.0589x over previous
#include <cuda_runtime.h>
#include <cuda_fp16.h>

#define DIM   128
#define NC    4
#define N_RNA_MAX  20000
#define N_PROT_MAX 5000
#define EDGES_PER_WARP_ITER 8
#define TARGET_ITERS 4

// Folded weights: M[j][d] = sum_c Wc[c][j] * w_rel[c][d]
__device__ float g_M[NC * DIM];
// fp16 copies of the gather tables: halves the L2 gather flow vs fp32.
__device__ __half g_rna [N_RNA_MAX  * DIM];
__device__ __half g_prot[N_PROT_MAX * DIM];

// Prologue: fold weights (first 512 threads) + convert tables to fp16.
__global__ __launch_bounds__(256) void prep_kernel(
    const float* __restrict__ rna, const float* __restrict__ prot,
    const float* __restrict__ w_rel, const float* __restrict__ w_cls,
    long long nRelem, long long nPelem)
{
    const long long i = (long long)blockIdx.x * blockDim.x + threadIdx.x;

    if (i < NC * DIM) {
        int j = (int)i / DIM, d = (int)i % DIM;
        float s = 0.f;
#pragma unroll
        for (int c = 0; c < NC; ++c)
            s += w_cls[c * NC + j] * w_rel[c * DIM + d];
        g_M[j * DIM + d] = s;
    }

    const long long base = i * 8;
    if (base >= nRelem + nPelem) return;
    const float* src;  __half* dst;  long long off;
    if (base < nRelem) { src = rna;  dst = g_rna;  off = base; }
    else               { src = prot; dst = g_prot; off = base - nRelem; }

    float4 f0 = *reinterpret_cast<const float4*>(src + off);
    float4 f1 = *reinterpret_cast<const float4*>(src + off + 4);
    __half2 h0 = __floats2half2_rn(f0.x, f0.y);
    __half2 h1 = __floats2half2_rn(f0.z, f0.w);
    __half2 h2 = __floats2half2_rn(f1.x, f1.y);
    __half2 h3 = __floats2half2_rn(f1.z, f1.w);
    uint4 o;
    o.x = *reinterpret_cast<unsigned*>(&h0);
    o.y = *reinterpret_cast<unsigned*>(&h1);
    o.z = *reinterpret_cast<unsigned*>(&h2);
    o.w = *reinterpret_cast<unsigned*>(&h3);
    *reinterpret_cast<uint4*>(dst + off) = o;
}

// Streaming 16B load (guaranteed-miss gathers: skip L1 allocate).
__device__ __forceinline__ uint4 ldg_na(const uint4* p) {
    uint4 v;
    asm("ld.global.L1::no_allocate.v4.u32 {%0,%1,%2,%3}, [%4];"
        : "=r"(v.x), "=r"(v.y), "=r"(v.z), "=r"(v.w) : "l"(p));
    return v;
}

// Class-split butterfly over lane bits 0-1 (3 shfl). Afterwards lane l holds
// class c = ((l&1)<<1)|((l>>1)&1) summed over its 4-lane group.
__device__ __forceinline__ float reduce_stage1(const float a[4], int lane) {
    float x = (lane & 1) ? a[0] : a[2];
    float y = (lane & 1) ? a[1] : a[3];
    float rx = __shfl_xor_sync(0xffffffffu, x, 1);
    float ry = __shfl_xor_sync(0xffffffffu, y, 1);
    float A = ((lane & 1) ? a[2] : a[0]) + rx;
    float B = ((lane & 1) ? a[3] : a[1]) + ry;
    float z = (lane & 2) ? A : B;
    float rz = __shfl_xor_sync(0xffffffffu, z, 2);
    return ((lane & 2) ? B : A) + rz;
}

// fp16 product, fp32 accumulate.
__device__ __forceinline__ void accum_edge(uint4 R, uint4 P,
                                           const float4 Ma[NC], const float4 Mb[NC],
                                           float a[NC]) {
    __half2 q0 = __hmul2(*reinterpret_cast<__half2*>(&R.x),
                         *reinterpret_cast<__half2*>(&P.x));
    __half2 q1 = __hmul2(*reinterpret_cast<__half2*>(&R.y),
                         *reinterpret_cast<__half2*>(&P.y));
    __half2 q2 = __hmul2(*reinterpret_cast<__half2*>(&R.z),
                         *reinterpret_cast<__half2*>(&P.z));
    __half2 q3 = __hmul2(*reinterpret_cast<__half2*>(&R.w),
                         *reinterpret_cast<__half2*>(&P.w));
    float2 f0 = __half22float2(q0);
    float2 f1 = __half22float2(q1);
    float2 f2 = __half22float2(q2);
    float2 f3 = __half22float2(q3);
#pragma unroll
    for (int j = 0; j < NC; ++j) {
        a[j] += f0.x * Ma[j].x + f0.y * Ma[j].y + f1.x * Ma[j].z + f1.y * Ma[j].w
              + f2.x * Mb[j].x + f2.y * Mb[j].y + f3.x * Mb[j].z + f3.y * Mb[j].w;
    }
}

// 16 lanes per edge; each halfwarp handles 4 edges per iteration (8/warp,
// all 8x16B gathers per lane issued up-front). Grid-stride loop amortizes
// the 2KB folded-weight register load (32 L1 wavefronts) over ~4 iterations.
__global__ __launch_bounds__(256) void edge_kernel(
    const int* __restrict__ ridx,
    const int* __restrict__ pidx,
    float* __restrict__ out,
    int E)
{
    const int lane = threadIdx.x & 31;
    const int h    = lane & 15;
    const int sub  = lane >> 4;
    const int warp0  = (blockIdx.x * blockDim.x + threadIdx.x) >> 5;
    const int nwarps = (gridDim.x * blockDim.x) >> 5;

    // Folded-weight slice (loaded once per warp): M[j][8h..8h+7].
    const float4* Mv = reinterpret_cast<const float4*>(g_M);
    float4 Ma[NC], Mb[NC];
#pragma unroll
    for (int j = 0; j < NC; ++j) {
        Ma[j] = Mv[j * (DIM / 4) + 2 * h];
        Mb[j] = Mv[j * (DIM / 4) + 2 * h + 1];
    }

    const uint4* rv = reinterpret_cast<const uint4*>(g_rna);
    const uint4* pv = reinterpret_cast<const uint4*>(g_prot);

    const int ngroups = (E + EDGES_PER_WARP_ITER - 1) / EDGES_PER_WARP_ITER;
    const int c = ((h & 1) << 1) | ((h >> 1) & 1);

    for (int w = warp0; w < ngroups; w += nwarps) {
        int e[4];
        uint4 R[4], P[4];
#pragma unroll
        for (int i = 0; i < 4; ++i) {
            e[i] = 8 * w + 4 * sub + i;
            const int ec = (e[i] < E) ? e[i] : 0;
            const int ri = ridx[ec];
            const int pi = pidx[ec];
            R[i] = ldg_na(rv + (long long)ri * 16 + h);
            P[i] = ldg_na(pv + (long long)pi * 16 + h);
        }

        float a[4][NC];
#pragma unroll
        for (int i = 0; i < 4; ++i) {
#pragma unroll
            for (int j = 0; j < NC; ++j) a[i][j] = 0.f;
            accum_edge(R[i], P[i], Ma, Mb, a[i]);
        }

#pragma unroll
        for (int i = 0; i < 4; ++i) {
            float S = reduce_stage1(a[i], lane);
            S += __shfl_xor_sync(0xffffffffu, S, 4);
            S += __shfl_xor_sync(0xffffffffu, S, 8);
            if (h < 4 && e[i] < E) out[4 * e[i] + c] = fmaxf(S, 0.f);
        }
    }
}

extern "C" void kernel_launch(void* const* d_in, const int* in_sizes, int n_in,
                              void* d_out, int out_size) {
    const float* rna  = (const float*)d_in[0];   // [20000,128] f32
    const float* prot = (const float*)d_in[1];   // [5000,128]  f32
    const int*   ridx = (const int*)d_in[2];     // [E] int32
    const int*   pidx = (const int*)d_in[3];     // [E] int32
    const float* wrel = (const float*)d_in[4];   // [4,128] f32
    const float* wcls = (const float*)d_in[5];   // [4,4]   f32
    float*       out  = (float*)d_out;           // [E,4]   f32

    const int E = in_sizes[2];
    const long long nRelem = in_sizes[0];
    const long long nPelem = in_sizes[1];

    const long long cvt_threads = (nRelem + nPelem + 7) / 8;
    const int prep_blocks = (int)((cvt_threads + 255) / 256);
    prep_kernel<<<prep_blocks, 256>>>(rna, prot, wrel, wcls, nRelem, nPelem);

    // ~TARGET_ITERS groups of 8 edges per warp; 8 warps per block.
    const long long groups = ((long long)E + EDGES_PER_WARP_ITER - 1)
                             / EDGES_PER_WARP_ITER;
    const long long warps_wanted = (groups + TARGET_ITERS - 1) / TARGET_ITERS;
    long long blocks = (warps_wanted + 7) / 8;
    if (blocks < 1) blocks = 1;
    edge_kernel<<<(int)blocks, 256>>>(ridx, pidx, out, E);
}